// round 7
// baseline (speedup 1.0000x reference)
#include <cuda_runtime.h>
#include <math.h>

__device__ double       g_sum = 0.0;
__device__ unsigned int g_cnt = 0;

#define FULLM 0xFFFFFFFFu

struct V3 { float x, y, z; };

__device__ __forceinline__ V3 ld3(const float* __restrict__ p) { return {p[0], p[1], p[2]}; }
__device__ __forceinline__ V3 vsub(V3 a, V3 b) { return {a.x - b.x, a.y - b.y, a.z - b.z}; }
__device__ __forceinline__ float vdot(V3 a, V3 b) { return a.x * b.x + a.y * b.y + a.z * b.z; }
__device__ __forceinline__ V3 vcross(V3 a, V3 b) {
    return {a.y * b.z - a.z * b.y,
            a.z * b.x - a.x * b.z,
            a.x * b.y - a.y * b.x};
}
__device__ __forceinline__ V3 face_normal(const float* __restrict__ q) {
    V3 t0 = ld3(q), t1 = ld3(q + 3), t2 = ld3(q + 6);
    V3 c = vcross(vsub(t0, t1), vsub(t0, t2));
    float s = rsqrtf(vdot(c, c));
    return {c.x * s, c.y * s, c.z * s};
}
__device__ __forceinline__ float tri_area(V3 p1, V3 p2, V3 p3) {
    V3 c = vcross(vsub(p2, p1), vsub(p3, p1));
    return 0.5f * sqrtf(vdot(c, c));
}

// Closed form of (pair*coeff).sum()/9 with x = na@(r1-r2), y = nb@(r1-r2).
__device__ __forceinline__ float edge_term(
    V3 u, V3 w, V3 na, V3 nb,
    const float* __restrict__ r1, const float* __restrict__ r2,
    float dv2, float asum)
{
    V3 x = {0, 0, 0}, y = {0, 0, 0};
    #pragma unroll
    for (int c = 0; c < 3; c++) {
        float d0 = r1[3 * c + 0] - r2[3 * c + 0];
        float d1 = r1[3 * c + 1] - r2[3 * c + 1];
        float d2 = r1[3 * c + 2] - r2[3 * c + 2];
        float ac = (c == 0) ? na.x : ((c == 1) ? na.y : na.z);
        float bc = (c == 0) ? nb.x : ((c == 1) ? nb.y : nb.z);
        x.x += ac * d0; x.y += ac * d1; x.z += ac * d2;
        y.x += bc * d0; y.y += bc * d1; y.z += bc * d2;
    }
    float en = (3.0f * (vdot(u, u) + vdot(w, w) + vdot(u, w))
              + vdot(x, x) + vdot(y, y) + vdot(x, y)) * (1.0f / 9.0f);
    return en * (dv2 / asum);
}

// One thread per grid cell (i,j); up to 3 interior edges per cell:
//   diagonal   (v10,v01): tri1(i,j)  vs tri2(i,j)
//   horizontal (v10,v11): tri2(i,j)  vs tri1(i+1,j)   [i < m-1]
//   vertical   (v11,v01): tri2(i,j)  vs tri1(i,j+1)   [j < m-1]
// tri1(i,j)=i*m+j, tri2(i,j)=m*m+i*m+j (m=n-1). Edge-endpoint "normals" are
// tp[vertex_id] blocks (reference indexes normals by vertex ids).
// ALL loads are unconditional with clamped in-bounds indices -> one big
// basic block, ~100 independent LDGs batched up front (high MLP). Only the
// three accumulation adds are predicated.
__global__ __launch_bounds__(256, 5)
void k_cell(const float* __restrict__ tp,     // (F,3,3)
            const float* __restrict__ rot,    // (F,3,3)
            const float* __restrict__ verts,  // (V,3)
            float* __restrict__ out,
            int n, int nblocks)
{
    const int m   = n - 1;
    const int tid = threadIdx.x;
    const int j   = blockIdx.x * blockDim.x + tid;
    const int i   = blockIdx.y;

    const int  jc    = min(j, m);        // vertex-column clamp
    const int  jf    = min(j, m - 1);    // face-column clamp
    const bool cell  = (j < m);
    const bool cellR = (j < m - 1);
    const bool cellD = (i < m - 1);

    const int v00 = i * n + jc;                      // <= (m-1)*n + m  < n*n
    const int v10 = v00 + n;
    const int v20 = min(i + 2, n - 1) * n + jc;      // clamped row (i=m-1 case)
    const int fT1 = i * m + jf;
    const int fT2 = m * m + fT1;
    const int fD  = min(i + 1, m - 1) * m + jf;
    const int fR  = fT1 + 1;                         // < 2*m*m always

    // ---- batched load phase (all unconditional, clamped, independent) ----
    V3 p00 = ld3(verts + 3 * (size_t)v00);
    V3 p01 = ld3(verts + 3 * (size_t)(v00 + 1));     // v00+1 < n*n
    V3 p02 = ld3(verts + 3 * (size_t)(min(jc + 2, m) + i * n));
    V3 p10 = ld3(verts + 3 * (size_t)v10);
    V3 p11 = ld3(verts + 3 * (size_t)(v10 + 1));
    V3 p20 = ld3(verts + 3 * (size_t)v20);

    const float* q1 = tp + 9 * (size_t)fT1;
    const float* q2 = tp + 9 * (size_t)fT2;
    const float* qd = tp + 9 * (size_t)fD;
    const float* qr = tp + 9 * (size_t)fR;
    V3 t1_1 = ld3(q1 + 3), t1_2 = ld3(q1 + 6);
    V3 t2_0 = ld3(q2),     t2_1 = ld3(q2 + 3), t2_2 = ld3(q2 + 6);
    V3 td_0 = ld3(qd),     td_2 = ld3(qd + 6);
    V3 tr_0 = ld3(qr),     tr_1 = ld3(qr + 3);

    V3 n10 = face_normal(tp + 9 * (size_t)v10);
    V3 n01 = face_normal(tp + 9 * (size_t)(v00 + 1));
    V3 n11 = face_normal(tp + 9 * (size_t)(v10 + 1));

    const float* rT1 = rot + 9 * (size_t)fT1;
    const float* rT2 = rot + 9 * (size_t)fT2;
    const float* rD  = rot + 9 * (size_t)fD;
    const float* rR  = rot + 9 * (size_t)fR;

    // ---- areas (from loaded vertex data) ----
    float aT1 = tri_area(p00, p10, p01);   // tri1(i,j)   = (v00,v10,v01)
    float aT2 = tri_area(p10, p11, p01);   // tri2(i,j)   = (v10,v11,v01)
    float aD  = tri_area(p10, p20, p11);   // tri1(i+1,j) = (v10,v20,v11)
    float aR  = tri_area(p01, p11, p02);   // tri1(i,j+1) = (v01,v11,v02)

    // ---- per-edge accumulation (fp32, matches reference arithmetic) ----
    float val = 0.0f;
    // diagonal edge (v10, v01)
    {
        V3 u = vsub(t1_1, t2_0), w = vsub(t1_2, t2_2), d = vsub(p10, p01);
        float t = edge_term(u, w, n10, n01, rT1, rT2, vdot(d, d), aT1 + aT2);
        val += cell ? t : 0.0f;
    }
    // horizontal edge (v10, v11) vs tri1(i+1, j)
    {
        V3 u = vsub(t2_0, td_0), w = vsub(t2_1, td_2), d = vsub(p10, p11);
        float t = edge_term(u, w, n10, n11, rT2, rD, vdot(d, d), aT2 + aD);
        val += (cell && cellD) ? t : 0.0f;
    }
    // vertical edge (v11, v01) vs tri1(i, j+1)
    {
        V3 u = vsub(t2_1, tr_1), w = vsub(t2_2, tr_0), d = vsub(p11, p01);
        float t = edge_term(u, w, n11, n01, rT2, rR, vdot(d, d), aT2 + aR);
        val += cellR ? t : 0.0f;
    }

    // ---- warp reduce (fp32) -> cross-warp (fp64) -> global atomic ----
    #pragma unroll
    for (int off = 16; off > 0; off >>= 1)
        val += __shfl_down_sync(FULLM, val, off);

    __shared__ double sh[8];
    __shared__ int s_last;
    int lane = tid & 31, wid = tid >> 5;
    if (lane == 0) sh[wid] = (double)val;
    __syncthreads();

    if (tid == 0) {
        double bsum = 0.0;
        #pragma unroll
        for (int w = 0; w < 8; w++) bsum += sh[w];
        atomicAdd(&g_sum, bsum);
        __threadfence();
        unsigned old = atomicAdd(&g_cnt, 1u);
        s_last = (old == (unsigned)(nblocks - 1)) ? 1 : 0;
    }
    __syncthreads();

    if (s_last && tid == 0) {
        out[0] = (float)g_sum;
        g_sum = 0.0;      // self-reset -> graph-replay safe
        g_cnt = 0;
    }
}

extern "C" void kernel_launch(void* const* d_in, const int* in_sizes, int n_in,
                              void* d_out, int out_size)
{
    const float* tp    = (const float*)d_in[0];   // (F,3,3)
    const float* rot   = (const float*)d_in[1];   // (F,3,3)
    const float* verts = (const float*)d_in[2];   // (1,V,3)

    int V = in_sizes[2] / 3;
    int n = (int)(sqrt((double)V) + 0.5);
    int m = n - 1;

    dim3 block(256, 1, 1);
    dim3 grid((m + 255) / 256, m, 1);
    int nblocks = grid.x * grid.y;

    k_cell<<<grid, block>>>(tp, rot, verts, (float*)d_out, n, nblocks);
}

// round 8
// speedup vs baseline: 1.3807x; 1.3807x over previous
#include <cuda_runtime.h>
#include <math.h>

__device__ double g_sum = 0.0;

#define FULLM 0xFFFFFFFFu

struct V3 { float x, y, z; };

__device__ __forceinline__ V3 ld3(const float* __restrict__ p) { return {p[0], p[1], p[2]}; }
__device__ __forceinline__ V3 vsub(V3 a, V3 b) { return {a.x - b.x, a.y - b.y, a.z - b.z}; }
__device__ __forceinline__ float vdot(V3 a, V3 b) { return a.x * b.x + a.y * b.y + a.z * b.z; }
__device__ __forceinline__ V3 vcross(V3 a, V3 b) {
    return {a.y * b.z - a.z * b.y,
            a.z * b.x - a.x * b.z,
            a.x * b.y - a.y * b.x};
}
__device__ __forceinline__ V3 face_normal(const float* __restrict__ q) {
    V3 t0 = ld3(q), t1 = ld3(q + 3), t2 = ld3(q + 6);
    V3 c = vcross(vsub(t0, t1), vsub(t0, t2));
    float s = rsqrtf(vdot(c, c));
    return {c.x * s, c.y * s, c.z * s};
}
__device__ __forceinline__ float tri_area(V3 p1, V3 p2, V3 p3) {
    V3 c = vcross(vsub(p2, p1), vsub(p3, p1));
    return 0.5f * sqrtf(vdot(c, c));
}

// Closed form of (pair*coeff).sum()/9 with x = na@(r1-r2), y = nb@(r1-r2).
__device__ __forceinline__ float edge_term(
    V3 u, V3 w, V3 na, V3 nb,
    const float* __restrict__ r1, const float* __restrict__ r2,
    float dv2, float asum)
{
    V3 x = {0, 0, 0}, y = {0, 0, 0};
    #pragma unroll
    for (int c = 0; c < 3; c++) {
        float d0 = r1[3 * c + 0] - r2[3 * c + 0];
        float d1 = r1[3 * c + 1] - r2[3 * c + 1];
        float d2 = r1[3 * c + 2] - r2[3 * c + 2];
        float ac = (c == 0) ? na.x : ((c == 1) ? na.y : na.z);
        float bc = (c == 0) ? nb.x : ((c == 1) ? nb.y : nb.z);
        x.x += ac * d0; x.y += ac * d1; x.z += ac * d2;
        y.x += bc * d0; y.y += bc * d1; y.z += bc * d2;
    }
    float en = (3.0f * (vdot(u, u) + vdot(w, w) + vdot(u, w))
              + vdot(x, x) + vdot(y, y) + vdot(x, y)) * (1.0f / 9.0f);
    return en * (dv2 / asum);
}

// One thread per grid cell (i,j); up to 3 interior edges per cell:
//   diagonal   (v10,v01): tri1(i,j)  vs tri2(i,j)
//   horizontal (v10,v11): tri2(i,j)  vs tri1(i+1,j)   [i < m-1]
//   vertical   (v11,v01): tri2(i,j)  vs tri1(i,j+1)   [j < m-1]
// tri1(i,j)=i*m+j, tri2(i,j)=m*m+i*m+j (m=n-1). Edge-endpoint "normals" come
// from tp[vertex_id] (reference indexes normals by vertex ids).
// Minimal conditional load set (measured-best in R4); lean per-block epilogue.
__global__ __launch_bounds__(256, 5)
void k_cell(const float* __restrict__ tp,     // (F,3,3)
            const float* __restrict__ rot,    // (F,3,3)
            const float* __restrict__ verts,  // (V,3)
            int n)
{
    const int m = n - 1;
    int j = blockIdx.x * blockDim.x + threadIdx.x;
    int i = blockIdx.y;
    float val = 0.0f;

    if (j < m) {
        int v00 = i * n + j;
        int v10 = v00 + n;
        int v01 = v00 + 1;
        int v11 = v10 + 1;

        int fT1 = i * m + j;
        int fT2 = m * m + fT1;

        V3 p00 = ld3(verts + 3 * (size_t)v00);
        V3 p10 = ld3(verts + 3 * (size_t)v10);
        V3 p01 = ld3(verts + 3 * (size_t)v01);
        V3 p11 = ld3(verts + 3 * (size_t)v11);

        float aT1 = tri_area(p00, p10, p01);
        float aT2 = tri_area(p10, p11, p01);

        const float* q1 = tp + 9 * (size_t)fT1;
        const float* q2 = tp + 9 * (size_t)fT2;
        V3 t1_1 = ld3(q1 + 3), t1_2 = ld3(q1 + 6);
        V3 t2_0 = ld3(q2),     t2_1 = ld3(q2 + 3), t2_2 = ld3(q2 + 6);

        V3 n10 = face_normal(tp + 9 * (size_t)v10);
        V3 n01 = face_normal(tp + 9 * (size_t)v01);
        V3 n11 = face_normal(tp + 9 * (size_t)v11);

        const float* r1 = rot + 9 * (size_t)fT1;
        const float* r2 = rot + 9 * (size_t)fT2;

        // diagonal edge (v10, v01)
        {
            V3 u = vsub(t1_1, t2_0), w = vsub(t1_2, t2_2), d = vsub(p10, p01);
            val += edge_term(u, w, n10, n01, r1, r2, vdot(d, d), aT1 + aT2);
        }
        // horizontal edge (v10, v11) vs tri1(i+1, j)
        if (i < m - 1) {
            int fD = fT1 + m;
            const float* qd = tp + 9 * (size_t)fD;
            V3 td_0 = ld3(qd), td_2 = ld3(qd + 6);
            V3 p20 = ld3(verts + 3 * (size_t)(v10 + n));
            float aD = tri_area(p10, p20, p11);
            V3 u = vsub(t2_0, td_0), w = vsub(t2_1, td_2), d = vsub(p10, p11);
            val += edge_term(u, w, n10, n11, r2, rot + 9 * (size_t)fD, vdot(d, d), aT2 + aD);
        }
        // vertical edge (v11, v01) vs tri1(i, j+1)
        if (j < m - 1) {
            int fR = fT1 + 1;
            const float* qr = tp + 9 * (size_t)fR;
            V3 tr_0 = ld3(qr), tr_1 = ld3(qr + 3);
            V3 p02 = ld3(verts + 3 * (size_t)(v01 + 1));
            float aR = tri_area(p01, p11, p02);
            V3 u = vsub(t2_1, tr_1), w = vsub(t2_2, tr_0), d = vsub(p11, p01);
            val += edge_term(u, w, n11, n01, r2, rot + 9 * (size_t)fR, vdot(d, d), aT2 + aR);
        }
    }

    // ---- warp reduce (fp32) -> cross-warp (fp64) -> one atomic per block ----
    #pragma unroll
    for (int off = 16; off > 0; off >>= 1)
        val += __shfl_down_sync(FULLM, val, off);

    __shared__ double sh[8];
    int lane = threadIdx.x & 31;
    int wid  = threadIdx.x >> 5;
    if (lane == 0) sh[wid] = (double)val;
    __syncthreads();
    if (threadIdx.x == 0) {
        double bsum = 0.0;
        #pragma unroll
        for (int w = 0; w < 8; w++) bsum += sh[w];
        atomicAdd(&g_sum, bsum);
    }
}

// Write result and reset accumulator for the next graph replay.
__global__ void k_fin(float* __restrict__ out) {
    out[0] = (float)g_sum;
    g_sum = 0.0;
}

extern "C" void kernel_launch(void* const* d_in, const int* in_sizes, int n_in,
                              void* d_out, int out_size)
{
    const float* tp    = (const float*)d_in[0];   // (F,3,3)
    const float* rot   = (const float*)d_in[1];   // (F,3,3)
    const float* verts = (const float*)d_in[2];   // (1,V,3)

    int V = in_sizes[2] / 3;
    int n = (int)(sqrt((double)V) + 0.5);
    int m = n - 1;

    dim3 block(256, 1, 1);
    dim3 grid((m + 255) / 256, m, 1);

    k_cell<<<grid, block>>>(tp, rot, verts, n);
    k_fin<<<1, 1>>>((float*)d_out);
}